// round 1
// baseline (speedup 1.0000x reference)
#include <cuda_runtime.h>
#include <cuda_bf16.h>
#include <cstdint>

#define B  4
#define N  65536
#define M  128
#define K_POS 128
#define K_NEG 384
#define NSAMP 512

// Output layout (float32, tuple flattened in order)
#define OFF_ROIS 0
#define OFF_LAB  (B*NSAMP*8)              // 16384
#define OFF_VAL  (OFF_LAB + B*NSAMP)      // 18432
#define OFF_ASG  (OFF_VAL + B*NSAMP)      // 20480
#define OFF_MAX  (OFF_ASG + B*N)          // 282624

// Scratch (no allocations allowed -> device globals)
__device__ unsigned g_gtmax[B * M];        // float bits, all IoUs >= +0
__device__ int      g_assigned[B * N];
__device__ unsigned g_topk[B * NSAMP];     // pos idx [0,128), neg idx [128,512)

__device__ __forceinline__ void st(float* out, long long idx, float v, long long lim) {
    if (idx < lim) out[idx] = v;
}

// IoU exactly matching the JAX op sequence, no FMA contraction.
__device__ __forceinline__ float iou_f(float4 bb, float ab, float4 g, float ag) {
    float ltx = fmaxf(bb.x, g.x);
    float lty = fmaxf(bb.y, g.y);
    float rbx = fminf(bb.z, g.z);
    float rby = fminf(bb.w, g.w);
    float w = fmaxf(__fsub_rn(rbx, ltx), 0.0f);
    float h = fmaxf(__fsub_rn(rby, lty), 0.0f);
    float inter = __fmul_rn(w, h);
    float u = __fadd_rn(ab, ag);
    u = __fsub_rn(u, inter);
    u = __fadd_rn(u, 1e-6f);
    return __fdiv_rn(inter, u);
}

__global__ void init_kernel() {
    int t = threadIdx.x;
    if (t < B * M) g_gtmax[t] = 0u;
}

// Pass 1: per-gt column max of IoU over all boxes.
__global__ void colmax_kernel(const float4* __restrict__ bboxes,
                              const float4* __restrict__ gts) {
    __shared__ float4  sgt[M];
    __shared__ float   sga[M];
    __shared__ unsigned scol[M];
    int b = blockIdx.y;
    int tid = threadIdx.x;
    if (tid < M) {
        float4 g = gts[b * M + tid];
        sgt[tid] = g;
        sga[tid] = __fmul_rn(__fsub_rn(g.z, g.x), __fsub_rn(g.w, g.y));
        scol[tid] = 0u;
    }
    __syncthreads();
    int n = blockIdx.x * 256 + tid;
    float4 bb = bboxes[(long long)b * N + n];
    float ab = __fmul_rn(__fsub_rn(bb.z, bb.x), __fsub_rn(bb.w, bb.y));
    int lane = tid & 31;
#pragma unroll 4
    for (int m = 0; m < M; m++) {
        float iou = iou_f(bb, ab, sgt[m], sga[m]);
        unsigned u = __float_as_uint(iou);        // iou >= +0 -> unsigned order OK
        unsigned wmax = __reduce_max_sync(0xffffffffu, u);
        if (lane == 0) atomicMax(&scol[m], wmax);
    }
    __syncthreads();
    if (tid < M) atomicMax(&g_gtmax[b * M + tid], scol[tid]);
}

// Pass 2: per-box max/argmax, low-quality match, final assignment.
__global__ void assign_kernel(const float4* __restrict__ bboxes,
                              const float4* __restrict__ gts,
                              float* __restrict__ out, long long lim) {
    __shared__ float4 sgt[M];
    __shared__ float  sga[M];
    __shared__ float  sgm[M];
    int b = blockIdx.y;
    int tid = threadIdx.x;
    if (tid < M) {
        float4 g = gts[b * M + tid];
        sgt[tid] = g;
        sga[tid] = __fmul_rn(__fsub_rn(g.z, g.x), __fsub_rn(g.w, g.y));
        sgm[tid] = __uint_as_float(g_gtmax[b * M + tid]);
    }
    __syncthreads();
    int n = blockIdx.x * 256 + tid;
    float4 bb = bboxes[(long long)b * N + n];
    float ab = __fmul_rn(__fsub_rn(bb.z, bb.x), __fsub_rn(bb.w, bb.y));
    float best = -1.0f;
    int bestm = 0;
    int lq = -1;
#pragma unroll 4
    for (int m = 0; m < M; m++) {
        float iou = iou_f(bb, ab, sgt[m], sga[m]);
        if (iou > best) { best = iou; bestm = m; }     // first-max (strict >)
        if (lq < 0) {
            float gm = sgm[m];
            if (gm >= 0.5f && iou == gm) lq = m;       // first matching gt
        }
    }
    int assigned = (lq >= 0) ? (lq + 1) : ((best >= 0.5f) ? (bestm + 1) : 0);
    long long o = (long long)b * N + n;
    g_assigned[o] = assigned;
    st(out, OFF_ASG + o, (float)assigned, lim);
    st(out, OFF_MAX + o, best, lim);
}

// Key: (float bits of prio [+10 if masked]) << 32 | ~index  -> all distinct,
// descending key order == jax.lax.top_k order (value desc, index asc).
__device__ __forceinline__ unsigned long long make_key(
        const float* __restrict__ pr, const int* __restrict__ asg,
        int n, int which) {
    int a = asg[n];
    bool msk = which ? (a == 0) : (a > 0);
    float v = pr[n];
    float val = msk ? __fadd_rn(v, 10.0f) : v;
    return ((unsigned long long)__float_as_uint(val) << 32)
         | (unsigned long long)(0xFFFFFFFFu - (unsigned)n);
}

#define TPK 1024
#define CAP 4096

__global__ void __launch_bounds__(TPK)
topk_kernel(const float* __restrict__ prio) {
    int task = blockIdx.x;
    int b = task >> 1;
    int which = task & 1;              // 0 = pos (K=128), 1 = neg (K=384)
    int K = which ? K_NEG : K_POS;
    const float* pr = prio + (long long)b * N;
    const int* asg = g_assigned + (long long)b * N;

    __shared__ unsigned hist[256];
    __shared__ unsigned sscan[256];
    __shared__ unsigned buf[CAP];
    __shared__ unsigned long long keys[NSAMP];
    __shared__ unsigned long long s_prefix;
    __shared__ int s_R, s_have, s_ncand, s_sel, s_selcnt, s_cnt;

    int tid = threadIdx.x;
    if (tid == 0) { s_R = K; s_have = 0; s_ncand = 0; s_prefix = 0ULL; }
    __syncthreads();

    for (int pass = 7; pass >= 0; --pass) {
        if (tid < 256) hist[tid] = 0u;
        __syncthreads();
        unsigned long long pref = s_prefix;
        if (s_have) {
            int nc = s_ncand;
            for (int i = tid; i < nc; i += TPK) {
                unsigned long long k = make_key(pr, asg, (int)buf[i], which);
                if ((k >> ((pass + 1) * 8)) == pref)
                    atomicAdd(&hist[(unsigned)(k >> (pass * 8)) & 255u], 1u);
            }
        } else {
            for (int n = tid; n < N; n += TPK) {   // N % TPK == 0: full warps
                unsigned long long k = make_key(pr, asg, n, which);
                bool ok = (pass == 7) || ((k >> ((pass + 1) * 8)) == pref);
                unsigned bin = ok ? ((unsigned)(k >> (pass * 8)) & 255u) : 0xFFFFFFFFu;
                unsigned mm = __match_any_sync(0xffffffffu, bin);
                int leader = __ffs(mm) - 1;
                if (ok && (tid & 31) == leader) atomicAdd(&hist[bin], (unsigned)__popc(mm));
            }
        }
        __syncthreads();
        // parallel suffix-sum over bins (count of keys in bins > d)
        if (tid < 256) sscan[tid] = hist[255 - tid];
        __syncthreads();
        for (int s = 1; s < 256; s <<= 1) {
            unsigned v = 0;
            if (tid < 256 && tid >= s) v = sscan[tid - s];
            __syncthreads();
            if (tid < 256) sscan[tid] += v;
            __syncthreads();
        }
        if (tid < 256) {
            int d = 255 - tid;
            unsigned incl = sscan[tid];
            unsigned excl = incl - hist[d];
            unsigned R = (unsigned)s_R;
            if (excl < R && R <= incl) {
                s_sel = d; s_selcnt = (int)hist[d]; s_R = (int)(R - excl);
            }
        }
        __syncthreads();
        if (tid == 0) s_prefix = (s_prefix << 8) | (unsigned long long)(unsigned)s_sel;
        __syncthreads();
        // one-time compaction of the boundary bin into a candidate list
        if (pass > 0 && !s_have && s_selcnt <= CAP) {
            unsigned long long p2 = s_prefix;
            for (int n = tid; n < N; n += TPK) {
                unsigned long long k = make_key(pr, asg, n, which);
                if ((k >> (pass * 8)) == p2) {
                    int p = atomicAdd(&s_ncand, 1);
                    if (p < CAP) buf[p] = (unsigned)n;
                }
            }
            __syncthreads();
            if (tid == 0) s_have = 1;
            __syncthreads();
        }
    }

    // collection: exactly K keys >= the Kth key (all keys distinct)
    if (tid == 0) s_cnt = 0;
    __syncthreads();
    unsigned long long kth = s_prefix;
    for (int n = tid; n < N; n += TPK) {
        unsigned long long k = make_key(pr, asg, n, which);
        if (k >= kth) {
            int p = atomicAdd(&s_cnt, 1);
            if (p < NSAMP) keys[p] = k;
        }
    }
    __syncthreads();
    int cnt = s_cnt;
    for (int i = tid; i < NSAMP; i += TPK)
        if (i >= cnt) keys[i] = 0ULL;
    __syncthreads();

    // bitonic sort, 512 elems, descending
    for (int kk = 2; kk <= NSAMP; kk <<= 1) {
        for (int j = kk >> 1; j > 0; j >>= 1) {
            __syncthreads();
            if (tid < NSAMP) {
                int l = tid ^ j;
                if (l > tid) {
                    unsigned long long a = keys[tid], c = keys[l];
                    bool desc = ((tid & kk) == 0);
                    if (desc ? (a < c) : (a > c)) { keys[tid] = c; keys[l] = a; }
                }
            }
        }
    }
    __syncthreads();
    int base = b * NSAMP + (which ? K_POS : 0);
    for (int i = tid; i < K; i += TPK)
        g_topk[base + i] = 0xFFFFFFFFu - (unsigned)(keys[i] & 0xFFFFFFFFull);
}

__global__ void gather_kernel(const float4* __restrict__ bboxes,
                              const float4* __restrict__ gts,
                              const int* __restrict__ labels,
                              float* __restrict__ out, long long lim) {
    int b = blockIdx.x;
    int i = threadIdx.x;     // 512
    unsigned idx = g_topk[b * NSAMP + i];
    float4 bb = bboxes[(long long)b * N + idx];
    int a = g_assigned[(long long)b * N + idx];
    float4 tgt = make_float4(0.f, 0.f, 0.f, 0.f);
    float lab, val;
    if (i < K_POS) {
        bool v = (a > 0);
        int gi = a - 1; if (gi < 0) gi = 0;
        if (v) {
            tgt = gts[b * M + gi];
            lab = (float)labels[b * M + gi];
        } else {
            lab = -1.0f;
        }
        val = v ? 1.0f : 0.0f;
    } else {
        lab = 0.0f;
        val = (a == 0) ? 1.0f : 0.0f;
    }
    long long r = (long long)(b * NSAMP + i);
    long long ro = OFF_ROIS + r * 8;
    st(out, ro + 0, bb.x, lim); st(out, ro + 1, bb.y, lim);
    st(out, ro + 2, bb.z, lim); st(out, ro + 3, bb.w, lim);
    st(out, ro + 4, tgt.x, lim); st(out, ro + 5, tgt.y, lim);
    st(out, ro + 6, tgt.z, lim); st(out, ro + 7, tgt.w, lim);
    st(out, OFF_LAB + r, lab, lim);
    st(out, OFF_VAL + r, val, lim);
}

extern "C" void kernel_launch(void* const* d_in, const int* in_sizes, int n_in,
                              void* d_out, int out_size) {
    const float4* bboxes = (const float4*)d_in[0];   // [B,N,4] f32
    const float4* gts    = (const float4*)d_in[1];   // [B,M,4] f32
    const int*    labels = (const int*)d_in[2];      // [B,M] i32
    const float*  prio   = (const float*)d_in[3];    // [B,N] f32
    float* out = (float*)d_out;
    long long lim = (long long)out_size;

    init_kernel<<<1, 512>>>();
    dim3 grid(N / 256, B);
    colmax_kernel<<<grid, 256>>>(bboxes, gts);
    assign_kernel<<<grid, 256>>>(bboxes, gts, out, lim);
    topk_kernel<<<2 * B, TPK>>>(prio);
    gather_kernel<<<B, NSAMP>>>(bboxes, gts, labels, out, lim);
}

// round 2
// speedup vs baseline: 2.0435x; 2.0435x over previous
#include <cuda_runtime.h>
#include <cuda_bf16.h>
#include <cstdint>

#define B  4
#define N  65536
#define M  128
#define K_POS 128
#define K_NEG 384
#define NSAMP 512

// Output layout (float32, tuple flattened in order)
#define OFF_ROIS 0
#define OFF_LAB  (B*NSAMP*8)              // 16384
#define OFF_VAL  (OFF_LAB + B*NSAMP)      // 18432
#define OFF_ASG  (OFF_VAL + B*NSAMP)      // 20480
#define OFF_MAX  (OFF_ASG + B*N)          // 282624

#define HI_CAP   (1<<18)
#define CAND_CAP 4096
#define NBIN     2048

// Scratch (no allocations allowed -> device globals)
__device__ unsigned g_gtmax[B * M];          // float bits of per-gt col max
__device__ int      g_assigned[B * N];       // prelim then final
__device__ unsigned g_lq[B * N];             // first matching gt (min m), ~0 = none
__device__ uint2    g_hi[B][HI_CAP];         // (n | m<<16, iou_bits) for iou>=0.5
__device__ int      g_hicnt[B];
__device__ unsigned g_hist[8 * NBIN];        // per-task value histogram
__device__ int      g_bt[8];                 // per-task threshold bin
__device__ unsigned long long g_cand[8][CAND_CAP];
__device__ int      g_ccnt[8];
__device__ unsigned g_topk[B * NSAMP];       // pos idx [0,128), neg idx [128,512)

__device__ __forceinline__ void st(float* out, long long idx, float v, long long lim) {
    if (idx < lim) out[idx] = v;
}

// IoU exactly matching the JAX op sequence, no FMA contraction. (rel_err==0 validated)
__device__ __forceinline__ float iou_f(float4 bb, float ab, float4 g, float ag) {
    float ltx = fmaxf(bb.x, g.x);
    float lty = fmaxf(bb.y, g.y);
    float rbx = fminf(bb.z, g.z);
    float rby = fminf(bb.w, g.w);
    float w = fmaxf(__fsub_rn(rbx, ltx), 0.0f);
    float h = fmaxf(__fsub_rn(rby, lty), 0.0f);
    float inter = __fmul_rn(w, h);
    float u = __fadd_rn(ab, ag);
    u = __fsub_rn(u, inter);
    u = __fadd_rn(u, 1e-6f);
    return __fdiv_rn(inter, u);
}

// Key: (float bits of prio [+10 if masked]) << 32 | ~index  -> all distinct,
// descending key order == jax.lax.top_k order (value desc, index asc).
__device__ __forceinline__ unsigned long long make_key(
        const float* __restrict__ pr, const int* __restrict__ asg,
        int n, int which) {
    int a = asg[n];
    bool msk = which ? (a == 0) : (a > 0);
    float v = pr[n];
    float val = msk ? __fadd_rn(v, 10.0f) : v;
    return ((unsigned long long)__float_as_uint(val) << 32)
         | (unsigned long long)(0xFFFFFFFFu - (unsigned)n);
}

__device__ __forceinline__ float masked_val(
        const float* __restrict__ pr, const int* __restrict__ asg,
        int n, int which) {
    int a = asg[n];
    bool msk = which ? (a == 0) : (a > 0);
    float v = pr[n];
    return msk ? __fadd_rn(v, 10.0f) : v;
}

// Monotone coarse bin of the value; splits the +10 clump into ~186 bins.
__device__ __forceinline__ int val_bin(float v) {
    int iv = (int)(__fmul_rn(v, 186.0f));   // v in [0, 11) -> [0, 2046]
    if (iv < 0) iv = 0;
    if (iv > NBIN - 1) iv = NBIN - 1;
    return iv;
}

// ---------------------------------------------------------------------------
__global__ void init_kernel() {
    int gid = blockIdx.x * 512 + threadIdx.x;      // 512x512 = 262144 = B*N
    g_lq[gid] = 0xFFFFFFFFu;
    if (gid < 8 * NBIN) g_hist[gid] = 0u;
    if (gid < B * M) g_gtmax[gid] = 0u;
    if (gid < 8) g_ccnt[gid] = 0;
    if (gid < B) g_hicnt[gid] = 0;
}

// ---------------------------------------------------------------------------
// Fused single IoU pass: per-box max/argmax (-> max_ov + prelim assigned),
// per-gt column max (REDUX + atomics), push (n,m) pairs with iou>=0.5.
__global__ void __launch_bounds__(256)
assign_fused_kernel(const float4* __restrict__ bboxes,
                    const float4* __restrict__ gts,
                    float* __restrict__ out, long long lim) {
    __shared__ float4  sgt[M];
    __shared__ float   sga[M];
    __shared__ unsigned scol[M];
    int b = blockIdx.y;
    int tid = threadIdx.x;
    if (tid < M) {
        float4 g = gts[b * M + tid];
        sgt[tid] = g;
        sga[tid] = __fmul_rn(__fsub_rn(g.z, g.x), __fsub_rn(g.w, g.y));
        scol[tid] = 0u;
    }
    __syncthreads();
    int n0 = blockIdx.x * 512 + tid;
    int n1 = n0 + 256;
    float4 bb0 = bboxes[(long long)b * N + n0];
    float4 bb1 = bboxes[(long long)b * N + n1];
    float ab0 = __fmul_rn(__fsub_rn(bb0.z, bb0.x), __fsub_rn(bb0.w, bb0.y));
    float ab1 = __fmul_rn(__fsub_rn(bb1.z, bb1.x), __fsub_rn(bb1.w, bb1.y));
    float best0 = -1.0f, best1 = -1.0f;
    int bm0 = 0, bm1 = 0;
    int lane = tid & 31;
#pragma unroll 4
    for (int m = 0; m < M; m++) {
        float4 g = sgt[m];
        float ag = sga[m];
        float i0 = iou_f(bb0, ab0, g, ag);
        float i1 = iou_f(bb1, ab1, g, ag);
        if (i0 > best0) { best0 = i0; bm0 = m; }
        if (i1 > best1) { best1 = i1; bm1 = m; }
        unsigned u0 = __float_as_uint(i0);
        unsigned u1 = __float_as_uint(i1);
        unsigned u = u0 > u1 ? u0 : u1;
        unsigned wmax = __reduce_max_sync(0xffffffffu, u);
        if (lane == 0) atomicMax(&scol[m], wmax);
        if (i0 >= 0.5f) {
            int p = atomicAdd(&g_hicnt[b], 1);
            if (p < HI_CAP) g_hi[b][p] = make_uint2((unsigned)n0 | ((unsigned)m << 16), u0);
        }
        if (i1 >= 0.5f) {
            int p = atomicAdd(&g_hicnt[b], 1);
            if (p < HI_CAP) g_hi[b][p] = make_uint2((unsigned)n1 | ((unsigned)m << 16), u1);
        }
    }
    __syncthreads();
    if (tid < M) atomicMax(&g_gtmax[b * M + tid], scol[tid]);

    long long o0 = (long long)b * N + n0;
    long long o1 = (long long)b * N + n1;
    g_assigned[o0] = (best0 >= 0.5f) ? (bm0 + 1) : 0;
    g_assigned[o1] = (best1 >= 0.5f) ? (bm1 + 1) : 0;
    st(out, OFF_MAX + o0, best0, lim);
    st(out, OFF_MAX + o1, best1, lim);
}

// ---------------------------------------------------------------------------
// Low-quality match: for each pushed pair whose iou bits equal the final
// gt col-max (>=0.5 by construction), record min m per box.
__global__ void lq_kernel() {
    int b = blockIdx.y;
    int c = g_hicnt[b];
    if (c > HI_CAP) c = HI_CAP;
    for (int i = blockIdx.x * 256 + threadIdx.x; i < c; i += 32 * 256) {
        uint2 e = g_hi[b][i];
        unsigned n = e.x & 0xFFFFu;
        unsigned m = e.x >> 16;
        if (e.y == g_gtmax[b * M + m])
            atomicMin(&g_lq[(long long)b * N + n], m);
    }
}

__global__ void finalize_kernel(float* __restrict__ out, long long lim) {
    int b = blockIdx.y;
    int n = blockIdx.x * 512 + threadIdx.x;
    long long o = (long long)b * N + n;
    unsigned lq = g_lq[o];
    int a = (lq != 0xFFFFFFFFu) ? (int)lq + 1 : g_assigned[o];
    g_assigned[o] = a;
    st(out, OFF_ASG + o, (float)a, lim);
}

// ---------------------------------------------------------------------------
// Top-k stage 1: per-task coarse histogram of masked values (256 blocks).
__global__ void __launch_bounds__(256)
hist_kernel(const float* __restrict__ prio) {
    __shared__ unsigned shist[NBIN];
    int task = blockIdx.y;
    int b = task >> 1, which = task & 1;
    int tid = threadIdx.x;
#pragma unroll
    for (int j = 0; j < NBIN / 256; j++) shist[tid + j * 256] = 0u;
    __syncthreads();
    const float* pr = prio + (long long)b * N;
    const int* asg = g_assigned + (long long)b * N;
    int base = blockIdx.x * 2048;
#pragma unroll
    for (int j = 0; j < 8; j++) {
        int n = base + j * 256 + tid;
        atomicAdd(&shist[val_bin(masked_val(pr, asg, n, which))], 1u);
    }
    __syncthreads();
#pragma unroll
    for (int j = 0; j < NBIN / 256; j++) {
        unsigned v = shist[tid + j * 256];
        if (v) atomicAdd(&g_hist[task * NBIN + tid + j * 256], v);
    }
}

// Stage 2: find threshold bin bt = largest bin d with count(bins >= d) >= K.
__global__ void __launch_bounds__(1024)
selectbin_kernel() {
    __shared__ unsigned s[NBIN];
    int task = blockIdx.x;
    int K = (task & 1) ? K_NEG : K_POS;
    int tid = threadIdx.x;
    // reversed copy: s[i] = hist[2047 - i]
    s[tid]        = g_hist[task * NBIN + (NBIN - 1 - tid)];
    s[tid + 1024] = g_hist[task * NBIN + (NBIN - 1 - (tid + 1024))];
    __syncthreads();
    // Hillis-Steele inclusive scan over 2048, 2 elems/thread
    for (int off = 1; off < NBIN; off <<= 1) {
        unsigned v0 = 0, v1 = 0;
        if (tid >= off) v0 = s[tid - off];
        if (tid + 1024 >= off) v1 = s[tid + 1024 - off];
        __syncthreads();
        s[tid] += v0;
        s[tid + 1024] += v1;
        __syncthreads();
    }
    // smallest i with s[i] >= K  ->  bt = 2047 - i
#pragma unroll
    for (int j = 0; j < 2; j++) {
        int i = tid + j * 1024;
        unsigned cur = s[i];
        unsigned prev = (i == 0) ? 0u : s[i - 1];
        if (cur >= (unsigned)K && prev < (unsigned)K)
            g_bt[task] = NBIN - 1 - i;
    }
}

// Stage 3: compact full 64-bit keys in bins >= bt (256 blocks).
__global__ void __launch_bounds__(256)
compact_kernel(const float* __restrict__ prio) {
    int task = blockIdx.y;
    int b = task >> 1, which = task & 1;
    int bt = g_bt[task];
    const float* pr = prio + (long long)b * N;
    const int* asg = g_assigned + (long long)b * N;
    int base = blockIdx.x * 2048;
#pragma unroll
    for (int j = 0; j < 8; j++) {
        int n = base + j * 256 + threadIdx.x;
        float v = masked_val(pr, asg, n, which);
        if (val_bin(v) >= bt) {
            int p = atomicAdd(&g_ccnt[task], 1);
            if (p < CAND_CAP)
                g_cand[task][p] =
                    ((unsigned long long)__float_as_uint(v) << 32)
                  | (unsigned long long)(0xFFFFFFFFu - (unsigned)n);
        }
    }
}

// Stage 4: bitonic-sort candidates desc (exact 64-bit keys), emit top-K indices.
__global__ void __launch_bounds__(1024)
sortsel_kernel() {
    __shared__ unsigned long long skeys[CAND_CAP];
    int task = blockIdx.x;
    int b = task >> 1, which = task & 1;
    int K = which ? K_NEG : K_POS;
    int tid = threadIdx.x;
    int nc = g_ccnt[task];
    if (nc > CAND_CAP) nc = CAND_CAP;
    int P = 512;
    while (P < nc) P <<= 1;
    for (int i = tid; i < P; i += 1024)
        skeys[i] = (i < nc) ? g_cand[task][i] : 0ULL;
    __syncthreads();
    for (int kk = 2; kk <= P; kk <<= 1) {
        for (int j = kk >> 1; j > 0; j >>= 1) {
            for (int i = tid; i < P; i += 1024) {
                int l = i ^ j;
                if (l > i) {
                    unsigned long long a = skeys[i], c = skeys[l];
                    bool desc = ((i & kk) == 0);
                    if (desc ? (a < c) : (a > c)) { skeys[i] = c; skeys[l] = a; }
                }
            }
            __syncthreads();
        }
    }
    int base = b * NSAMP + (which ? K_POS : 0);
    for (int i = tid; i < K; i += 1024)
        g_topk[base + i] = 0xFFFFFFFFu - (unsigned)(skeys[i] & 0xFFFFFFFFull);
}

// ---------------------------------------------------------------------------
__global__ void gather_kernel(const float4* __restrict__ bboxes,
                              const float4* __restrict__ gts,
                              const int* __restrict__ labels,
                              float* __restrict__ out, long long lim) {
    int b = blockIdx.x;
    int i = threadIdx.x;     // 512
    unsigned idx = g_topk[b * NSAMP + i];
    float4 bb = bboxes[(long long)b * N + idx];
    int a = g_assigned[(long long)b * N + idx];
    float4 tgt = make_float4(0.f, 0.f, 0.f, 0.f);
    float lab, val;
    if (i < K_POS) {
        bool v = (a > 0);
        int gi = a - 1; if (gi < 0) gi = 0;
        if (v) {
            tgt = gts[b * M + gi];
            lab = (float)labels[b * M + gi];
        } else {
            lab = -1.0f;
        }
        val = v ? 1.0f : 0.0f;
    } else {
        lab = 0.0f;
        val = (a == 0) ? 1.0f : 0.0f;
    }
    long long r = (long long)(b * NSAMP + i);
    long long ro = OFF_ROIS + r * 8;
    st(out, ro + 0, bb.x, lim); st(out, ro + 1, bb.y, lim);
    st(out, ro + 2, bb.z, lim); st(out, ro + 3, bb.w, lim);
    st(out, ro + 4, tgt.x, lim); st(out, ro + 5, tgt.y, lim);
    st(out, ro + 6, tgt.z, lim); st(out, ro + 7, tgt.w, lim);
    st(out, OFF_LAB + r, lab, lim);
    st(out, OFF_VAL + r, val, lim);
}

extern "C" void kernel_launch(void* const* d_in, const int* in_sizes, int n_in,
                              void* d_out, int out_size) {
    const float4* bboxes = (const float4*)d_in[0];   // [B,N,4] f32
    const float4* gts    = (const float4*)d_in[1];   // [B,M,4] f32
    const int*    labels = (const int*)d_in[2];      // [B,M] i32
    const float*  prio   = (const float*)d_in[3];    // [B,N] f32
    float* out = (float*)d_out;
    long long lim = (long long)out_size;

    init_kernel<<<512, 512>>>();
    assign_fused_kernel<<<dim3(N / 512, B), 256>>>(bboxes, gts, out, lim);
    lq_kernel<<<dim3(32, B), 256>>>();
    finalize_kernel<<<dim3(N / 512, B), 512>>>(out, lim);
    hist_kernel<<<dim3(N / 2048, 8), 256>>>(prio);
    selectbin_kernel<<<8, 1024>>>();
    compact_kernel<<<dim3(N / 2048, 8), 256>>>(prio);
    sortsel_kernel<<<8, 1024>>>();
    gather_kernel<<<B, NSAMP>>>(bboxes, gts, labels, out, lim);
}

// round 3
// speedup vs baseline: 2.2719x; 1.1118x over previous
#include <cuda_runtime.h>
#include <cuda_bf16.h>
#include <cstdint>

#define B  4
#define N  65536
#define M  128
#define K_POS 128
#define K_NEG 384
#define NSAMP 512

// Output layout (float32, tuple flattened in order)
#define OFF_ROIS 0
#define OFF_LAB  (B*NSAMP*8)              // 16384
#define OFF_VAL  (OFF_LAB + B*NSAMP)      // 18432
#define OFF_ASG  (OFF_VAL + B*NSAMP)      // 20480
#define OFF_MAX  (OFF_ASG + B*N)          // 282624

#define HI_CAP   (1<<18)
#define CAND_CAP 4096
#define NBIN     2048

// Scratch: all zero-initialized at module load; every consumer resets what it
// reads so graph replays see the same initial state (no init kernel needed).
__device__ int      g_assigned[B * N];       // prelim then final (fully overwritten)
__device__ unsigned g_lqv[B * N];            // M - m of first matching gt; 0 = none
__device__ uint2    g_hi[B][HI_CAP];         // (n | m<<16, iou_bits) for iou>=0.5
__device__ int      g_hicnt[B];
__device__ unsigned g_hist[8 * NBIN];        // per-task value histogram
__device__ unsigned long long g_cand[8][CAND_CAP];
__device__ int      g_ccnt[8];

__device__ __forceinline__ void st(float* out, long long idx, float v, long long lim) {
    if (idx < lim) out[idx] = v;
}

// IoU exactly matching the JAX op sequence, no FMA contraction. (rel_err==0 validated)
__device__ __forceinline__ float iou_f(float4 bb, float ab, float4 g, float ag) {
    float ltx = fmaxf(bb.x, g.x);
    float lty = fmaxf(bb.y, g.y);
    float rbx = fminf(bb.z, g.z);
    float rby = fminf(bb.w, g.w);
    float w = fmaxf(__fsub_rn(rbx, ltx), 0.0f);
    float h = fmaxf(__fsub_rn(rby, lty), 0.0f);
    float inter = __fmul_rn(w, h);
    float u = __fadd_rn(ab, ag);
    u = __fsub_rn(u, inter);
    u = __fadd_rn(u, 1e-6f);
    return __fdiv_rn(inter, u);
}

// Monotone coarse bin; splits the +10 clump into ~186 bins.
__device__ __forceinline__ int val_bin(float v) {
    int iv = (int)(__fmul_rn(v, 186.0f));   // v in [0, 11) -> [0, 2046]
    if (iv < 0) iv = 0;
    if (iv > NBIN - 1) iv = NBIN - 1;
    return iv;
}

// ---------------------------------------------------------------------------
// Single IoU pass: per-box max/argmax (-> max_ov + prelim assigned),
// push (n,m,iou_bits) pairs with iou>=0.5. No column-max work in the loop.
__global__ void __launch_bounds__(256)
assign_fused_kernel(const float4* __restrict__ bboxes,
                    const float4* __restrict__ gts,
                    float* __restrict__ out, long long lim) {
    __shared__ float4 sgt[M];
    __shared__ float  sga[M];
    int b = blockIdx.y;
    int tid = threadIdx.x;
    if (tid < M) {
        float4 g = gts[b * M + tid];
        sgt[tid] = g;
        sga[tid] = __fmul_rn(__fsub_rn(g.z, g.x), __fsub_rn(g.w, g.y));
    }
    __syncthreads();
    int n0 = blockIdx.x * 512 + tid;
    int n1 = n0 + 256;
    float4 bb0 = bboxes[(long long)b * N + n0];
    float4 bb1 = bboxes[(long long)b * N + n1];
    float ab0 = __fmul_rn(__fsub_rn(bb0.z, bb0.x), __fsub_rn(bb0.w, bb0.y));
    float ab1 = __fmul_rn(__fsub_rn(bb1.z, bb1.x), __fsub_rn(bb1.w, bb1.y));
    float best0 = -1.0f, best1 = -1.0f;
    int bm0 = 0, bm1 = 0;
#pragma unroll 4
    for (int m = 0; m < M; m++) {
        float4 g = sgt[m];
        float ag = sga[m];
        float i0 = iou_f(bb0, ab0, g, ag);
        float i1 = iou_f(bb1, ab1, g, ag);
        if (i0 > best0) { best0 = i0; bm0 = m; }   // first-max (strict >)
        if (i1 > best1) { best1 = i1; bm1 = m; }
        if (i0 >= 0.5f) {
            int p = atomicAdd(&g_hicnt[b], 1);
            if (p < HI_CAP)
                g_hi[b][p] = make_uint2((unsigned)n0 | ((unsigned)m << 16),
                                        __float_as_uint(i0));
        }
        if (i1 >= 0.5f) {
            int p = atomicAdd(&g_hicnt[b], 1);
            if (p < HI_CAP)
                g_hi[b][p] = make_uint2((unsigned)n1 | ((unsigned)m << 16),
                                        __float_as_uint(i1));
        }
    }
    long long o0 = (long long)b * N + n0;
    long long o1 = (long long)b * N + n1;
    g_assigned[o0] = (best0 >= 0.5f) ? (bm0 + 1) : 0;
    g_assigned[o1] = (best1 >= 0.5f) ? (bm1 + 1) : 0;
    st(out, OFF_MAX + o0, best0, lim);
    st(out, OFF_MAX + o1, best1, lim);
}

// ---------------------------------------------------------------------------
// LQ match from candidates: reconstruct per-gt column max (exact where >=0.5,
// which is the only regime that matters), then record first matching gt per box.
__global__ void __launch_bounds__(1024)
lq_refine_kernel() {
    __shared__ unsigned sgm[M];
    int b = blockIdx.x;
    int tid = threadIdx.x;
    if (tid < M) sgm[tid] = 0u;
    __syncthreads();
    int c = g_hicnt[b];
    if (c > HI_CAP) c = HI_CAP;
    for (int i = tid; i < c; i += 1024) {
        uint2 e = g_hi[b][i];
        atomicMax(&sgm[e.x >> 16], e.y);
    }
    __syncthreads();
    for (int i = tid; i < c; i += 1024) {
        uint2 e = g_hi[b][i];
        unsigned m = e.x >> 16;
        if (e.y == sgm[m])
            atomicMax(&g_lqv[(long long)b * N + (e.x & 0xFFFFu)], (unsigned)(M - (int)m));
    }
    __syncthreads();
    if (tid == 0) g_hicnt[b] = 0;           // reset for next replay
}

// ---------------------------------------------------------------------------
// Finalize assignment + build both masked-value histograms in one pass.
__global__ void __launch_bounds__(512)
finalize_hist_kernel(const float* __restrict__ prio,
                     float* __restrict__ out, long long lim) {
    __shared__ unsigned hp[NBIN];
    __shared__ unsigned hn[NBIN];
    int b = blockIdx.y;
    int tid = threadIdx.x;
#pragma unroll
    for (int j = 0; j < NBIN / 512; j++) {
        hp[tid + j * 512] = 0u;
        hn[tid + j * 512] = 0u;
    }
    __syncthreads();
    const float* pr = prio + (long long)b * N;
#pragma unroll
    for (int j = 0; j < 4; j++) {
        int n = blockIdx.x * 2048 + j * 512 + tid;
        long long o = (long long)b * N + n;
        int a = g_assigned[o];
        unsigned lv = g_lqv[o];
        if (lv) { a = (M - (int)lv) + 1; g_lqv[o] = 0u; }   // apply + reset
        g_assigned[o] = a;
        st(out, OFF_ASG + o, (float)a, lim);
        float v = pr[n];
        float vp = (a > 0)  ? __fadd_rn(v, 10.0f) : v;
        float vn = (a == 0) ? __fadd_rn(v, 10.0f) : v;
        atomicAdd(&hp[val_bin(vp)], 1u);
        atomicAdd(&hn[val_bin(vn)], 1u);
    }
    __syncthreads();
#pragma unroll
    for (int j = 0; j < NBIN / 512; j++) {
        int k = tid + j * 512;
        unsigned vp = hp[k], vn = hn[k];
        if (vp) atomicAdd(&g_hist[(2 * b) * NBIN + k], vp);
        if (vn) atomicAdd(&g_hist[(2 * b + 1) * NBIN + k], vn);
    }
}

// ---------------------------------------------------------------------------
// Each block recomputes the threshold bin from the histogram (cheap, avoids a
// launch), then compacts full 64-bit keys in bins >= bt.
__global__ void __launch_bounds__(256)
compact_kernel(const float* __restrict__ prio) {
    __shared__ unsigned sh[NBIN];
    __shared__ unsigned ss[256];
    __shared__ int sbt;
    int task = blockIdx.y;
    int b = task >> 1, which = task & 1;
    unsigned K = which ? K_NEG : K_POS;
    int tid = threadIdx.x;
#pragma unroll
    for (int j = 0; j < NBIN / 256; j++)
        sh[tid + j * 256] = g_hist[task * NBIN + tid + j * 256];
    __syncthreads();
    // chunk sums (8 bins per thread), inclusive suffix-scan over chunks
    unsigned cs = 0;
#pragma unroll
    for (int j = 0; j < 8; j++) cs += sh[tid * 8 + j];
    ss[tid] = cs;
    __syncthreads();
    for (int off = 1; off < 256; off <<= 1) {
        unsigned v = (tid + off < 256) ? ss[tid + off] : 0u;
        __syncthreads();
        ss[tid] += v;
        __syncthreads();
    }
    // bt = largest bin d with count(bins >= d) >= K
    {
        unsigned cum = (tid == 255) ? 0u : ss[tid + 1];
        for (int d = tid * 8 + 7; d >= tid * 8; --d) {
            unsigned nc = cum + sh[d];
            if (nc >= K && cum < K) sbt = d;
            cum = nc;
        }
    }
    __syncthreads();
    int bt = sbt;
    const float* pr = prio + (long long)b * N;
    const int* asg = g_assigned + (long long)b * N;
    int base = blockIdx.x * 2048;
#pragma unroll
    for (int j = 0; j < 8; j++) {
        int n = base + j * 256 + tid;
        int a = asg[n];
        bool msk = which ? (a == 0) : (a > 0);
        float v = pr[n];
        float val = msk ? __fadd_rn(v, 10.0f) : v;
        if (val_bin(val) >= bt) {
            int p = atomicAdd(&g_ccnt[task], 1);
            if (p < CAND_CAP)
                g_cand[task][p] =
                    ((unsigned long long)__float_as_uint(val) << 32)
                  | (unsigned long long)(0xFFFFFFFFu - (unsigned)n);
        }
    }
}

// ---------------------------------------------------------------------------
// Sort candidates desc (exact 64-bit keys: value desc, index asc = JAX order),
// then write the sampled output rows directly. Resets hist/ccnt.
__global__ void __launch_bounds__(1024)
sortsel_gather_kernel(const float4* __restrict__ bboxes,
                      const float4* __restrict__ gts,
                      const int* __restrict__ labels,
                      float* __restrict__ out, long long lim) {
    __shared__ unsigned long long skeys[CAND_CAP];
    int task = blockIdx.x;
    int b = task >> 1, which = task & 1;
    int K = which ? K_NEG : K_POS;
    int tid = threadIdx.x;
    int nc = g_ccnt[task];
    if (nc > CAND_CAP) nc = CAND_CAP;
    int P = 512;
    while (P < nc) P <<= 1;
    for (int i = tid; i < P; i += 1024)
        skeys[i] = (i < nc) ? g_cand[task][i] : 0ULL;
    __syncthreads();
    for (int kk = 2; kk <= P; kk <<= 1) {
        for (int j = kk >> 1; j > 0; j >>= 1) {
            for (int i = tid; i < P; i += 1024) {
                int l = i ^ j;
                if (l > i) {
                    unsigned long long a = skeys[i], c = skeys[l];
                    bool desc = ((i & kk) == 0);
                    if (desc ? (a < c) : (a > c)) { skeys[i] = c; skeys[l] = a; }
                }
            }
            __syncthreads();
        }
    }
    // emit rows
    for (int i = tid; i < K; i += 1024) {
        unsigned idx = 0xFFFFFFFFu - (unsigned)(skeys[i] & 0xFFFFFFFFull);
        float4 bb = bboxes[(long long)b * N + idx];
        int a = g_assigned[(long long)b * N + idx];
        float4 tgt = make_float4(0.f, 0.f, 0.f, 0.f);
        float lab, val;
        int row;
        if (!which) {
            row = i;
            bool v = (a > 0);
            int gi = a - 1; if (gi < 0) gi = 0;
            if (v) {
                tgt = gts[b * M + gi];
                lab = (float)labels[b * M + gi];
            } else {
                lab = -1.0f;
            }
            val = v ? 1.0f : 0.0f;
        } else {
            row = K_POS + i;
            lab = 0.0f;
            val = (a == 0) ? 1.0f : 0.0f;
        }
        long long r = (long long)(b * NSAMP + row);
        long long ro = OFF_ROIS + r * 8;
        st(out, ro + 0, bb.x, lim); st(out, ro + 1, bb.y, lim);
        st(out, ro + 2, bb.z, lim); st(out, ro + 3, bb.w, lim);
        st(out, ro + 4, tgt.x, lim); st(out, ro + 5, tgt.y, lim);
        st(out, ro + 6, tgt.z, lim); st(out, ro + 7, tgt.w, lim);
        st(out, OFF_LAB + r, lab, lim);
        st(out, OFF_VAL + r, val, lim);
    }
    // resets for next replay
    __syncthreads();
    for (int i = tid; i < NBIN; i += 1024) g_hist[task * NBIN + i] = 0u;
    if (tid == 0) g_ccnt[task] = 0;
}

extern "C" void kernel_launch(void* const* d_in, const int* in_sizes, int n_in,
                              void* d_out, int out_size) {
    const float4* bboxes = (const float4*)d_in[0];   // [B,N,4] f32
    const float4* gts    = (const float4*)d_in[1];   // [B,M,4] f32
    const int*    labels = (const int*)d_in[2];      // [B,M] i32
    const float*  prio   = (const float*)d_in[3];    // [B,N] f32
    float* out = (float*)d_out;
    long long lim = (long long)out_size;

    assign_fused_kernel<<<dim3(N / 512, B), 256>>>(bboxes, gts, out, lim);
    lq_refine_kernel<<<B, 1024>>>();
    finalize_hist_kernel<<<dim3(N / 2048, B), 512>>>(prio, out, lim);
    compact_kernel<<<dim3(N / 2048, 8), 256>>>(prio);
    sortsel_gather_kernel<<<8, 1024>>>(bboxes, gts, labels, out, lim);
}

// round 4
// speedup vs baseline: 2.8776x; 1.2666x over previous
#include <cuda_runtime.h>
#include <cuda_bf16.h>
#include <cstdint>

#define B  4
#define N  65536
#define M  128
#define K_POS 128
#define K_NEG 384
#define NSAMP 512

// Output layout (float32, tuple flattened in order)
#define OFF_ROIS 0
#define OFF_LAB  (B*NSAMP*8)              // 16384
#define OFF_VAL  (OFF_LAB + B*NSAMP)      // 18432
#define OFF_ASG  (OFF_VAL + B*NSAMP)      // 20480
#define OFF_MAX  (OFF_ASG + B*N)          // 282624

#define HI_CAP   (1<<18)
#define CAND_CAP 4096
#define NBIN     2048
#define FBLOCKS  ((N/2048)*B)             // finalize grid size = 128

// Scratch: zero-initialized at load; every consumer resets what it reads so
// graph replays see identical initial state.
__device__ int      g_assigned[B * N];
__device__ unsigned g_lqv[B * N];            // M - m of first matching gt; 0 = none
__device__ uint2    g_hi[B][HI_CAP];         // (n | m<<16, iou_bits) for iou>=0.5
__device__ int      g_hicnt[B];
__device__ unsigned g_hist[8 * NBIN];
__device__ int      g_bt[8];
__device__ unsigned g_fdone;
__device__ unsigned long long g_cand[8][CAND_CAP];
__device__ int      g_ccnt[8];

__device__ __forceinline__ void st(float* out, long long idx, float v, long long lim) {
    if (idx < lim) out[idx] = v;
}

// Exact IoU matching the JAX op sequence (validated rel_err==0).
__device__ __forceinline__ float iou_exact(float4 bb, float ab, float4 g, float ag) {
    float ltx = fmaxf(bb.x, g.x);
    float lty = fmaxf(bb.y, g.y);
    float rbx = fminf(bb.z, g.z);
    float rby = fminf(bb.w, g.w);
    float w = fmaxf(__fsub_rn(rbx, ltx), 0.0f);
    float h = fmaxf(__fsub_rn(rby, lty), 0.0f);
    float inter = __fmul_rn(w, h);
    float u = __fadd_rn(ab, ag);
    u = __fsub_rn(u, inter);
    u = __fadd_rn(u, 1e-6f);
    return __fdiv_rn(inter, u);
}

// inter and union with the exact reference rounding order.
__device__ __forceinline__ void iou_parts(float4 bb, float ab, float4 g, float ag,
                                          float& inter, float& u) {
    float ltx = fmaxf(bb.x, g.x);
    float lty = fmaxf(bb.y, g.y);
    float rbx = fminf(bb.z, g.z);
    float rby = fminf(bb.w, g.w);
    float w = fmaxf(__fsub_rn(rbx, ltx), 0.0f);
    float h = fmaxf(__fsub_rn(rby, lty), 0.0f);
    inter = __fmul_rn(w, h);
    float uu = __fadd_rn(ab, ag);
    uu = __fsub_rn(uu, inter);
    u = __fadd_rn(uu, 1e-6f);
}

__device__ __forceinline__ int val_bin(float v) {
    int iv = (int)(__fmul_rn(v, 186.0f));   // v in [0, 11) -> [0, 2046]
    if (iv < 0) iv = 0;
    if (iv > NBIN - 1) iv = NBIN - 1;
    return iv;
}

// ---------------------------------------------------------------------------
// Division-free assignment mainloop. Running max kept as the (inter, union)
// pair; candidate comparison via cross-multiplication with an ambiguity
// margin; ambiguous lanes (rare) rerun exactly. Pushes (iou>=0.5) gated by a
// conservative pre-test + exact divide; ballot-aggregated counter atomics.
__global__ void __launch_bounds__(256)
assign_fused_kernel(const float4* __restrict__ bboxes,
                    const float4* __restrict__ gts,
                    float* __restrict__ out, long long lim) {
    __shared__ float4 sgt[M];
    __shared__ float  sga[M];
    int b = blockIdx.y;
    int tid = threadIdx.x;
    if (tid < M) {
        float4 g = gts[b * M + tid];
        sgt[tid] = g;
        sga[tid] = __fmul_rn(__fsub_rn(g.z, g.x), __fsub_rn(g.w, g.y));
    }
    __syncthreads();
    int n0 = blockIdx.x * 512 + tid;
    int n1 = n0 + 256;
    float4 bb0 = bboxes[(long long)b * N + n0];
    float4 bb1 = bboxes[(long long)b * N + n1];
    float ab0 = __fmul_rn(__fsub_rn(bb0.z, bb0.x), __fsub_rn(bb0.w, bb0.y));
    float ab1 = __fmul_rn(__fsub_rn(bb1.z, bb1.x), __fsub_rn(bb1.w, bb1.y));
    float ib0 = 0.0f, ub0 = 1.0f, ib1 = 0.0f, ub1 = 1.0f;
    int bm0 = 0, bm1 = 0;
    bool amb0 = false, amb1 = false;
    int lane = tid & 31;
    unsigned lml = (1u << lane) - 1u;

#pragma unroll 4
    for (int m = 0; m < M; m++) {
        float4 g = sgt[m];
        float ag = sga[m];
        float i0, u0, i1, u1;
        iou_parts(bb0, ab0, g, ag, i0, u0);
        iou_parts(bb1, ab1, g, ag, i1, u1);
        // cross-mult compare vs running best (real-order; amb margin covers
        // any case where rounded-quotient order could differ)
        float x0 = __fmul_rn(i0, ub0), y0 = __fmul_rn(ib0, u0);
        float x1 = __fmul_rn(i1, ub1), y1 = __fmul_rn(ib1, u1);
        float d0 = __fsub_rn(x0, y0);
        float d1 = __fsub_rn(x1, y1);
        amb0 |= (fabsf(d0) < __fmul_rn(fmaxf(x0, y0), 1.5e-6f));
        amb1 |= (fabsf(d1) < __fmul_rn(fmaxf(x1, y1), 1.5e-6f));
        if (d0 > 0.0f) { ib0 = i0; ub0 = u0; bm0 = m; }
        if (d1 > 0.0f) { ib1 = i1; ub1 = u1; bm1 = m; }
        // conservative superset of {rn(i/u) >= 0.5}
        bool p0 = (i0 >= __fmul_rn(u0, 0.4999999f));
        bool p1 = (i1 >= __fmul_rn(u1, 0.4999999f));
        if (__any_sync(0xffffffffu, p0 || p1)) {
            float q0 = p0 ? __fdiv_rn(i0, u0) : 0.0f;
            float q1 = p1 ? __fdiv_rn(i1, u1) : 0.0f;
            bool w0 = p0 && (q0 >= 0.5f);
            bool w1 = p1 && (q1 >= 0.5f);
            unsigned mk0 = __ballot_sync(0xffffffffu, w0);
            unsigned mk1 = __ballot_sync(0xffffffffu, w1);
            int c0 = __popc(mk0);
            int tot = c0 + __popc(mk1);
            int base = 0;
            if (lane == 0 && tot) base = atomicAdd(&g_hicnt[b], tot);
            base = __shfl_sync(0xffffffffu, base, 0);
            if (w0) {
                int p = base + __popc(mk0 & lml);
                if (p < HI_CAP)
                    g_hi[b][p] = make_uint2((unsigned)n0 | ((unsigned)m << 16),
                                            __float_as_uint(q0));
            }
            if (w1) {
                int p = base + c0 + __popc(mk1 & lml);
                if (p < HI_CAP)
                    g_hi[b][p] = make_uint2((unsigned)n1 | ((unsigned)m << 16),
                                            __float_as_uint(q1));
            }
        }
    }
    // exact final quotient (one divide per box); rare ambiguous lanes rerun
    float q0, q1;
    if (amb0) {
        float bq = -1.0f; int bmm = 0;
        for (int m = 0; m < M; m++) {
            float q = iou_exact(bb0, ab0, sgt[m], sga[m]);
            if (q > bq) { bq = q; bmm = m; }
        }
        q0 = bq; bm0 = bmm;
    } else {
        q0 = __fdiv_rn(ib0, ub0);
    }
    if (amb1) {
        float bq = -1.0f; int bmm = 0;
        for (int m = 0; m < M; m++) {
            float q = iou_exact(bb1, ab1, sgt[m], sga[m]);
            if (q > bq) { bq = q; bmm = m; }
        }
        q1 = bq; bm1 = bmm;
    } else {
        q1 = __fdiv_rn(ib1, ub1);
    }
    long long o0 = (long long)b * N + n0;
    long long o1 = (long long)b * N + n1;
    g_assigned[o0] = (q0 >= 0.5f) ? (bm0 + 1) : 0;
    g_assigned[o1] = (q1 >= 0.5f) ? (bm1 + 1) : 0;
    st(out, OFF_MAX + o0, q0, lim);
    st(out, OFF_MAX + o1, q1, lim);
}

// ---------------------------------------------------------------------------
// LQ match from candidates: reconstruct per-gt column max (exact where >=0.5),
// record first matching gt (max of M-m) per box.
__global__ void __launch_bounds__(1024)
lq_refine_kernel() {
    __shared__ unsigned sgm[M];
    int b = blockIdx.x;
    int tid = threadIdx.x;
    if (tid < M) sgm[tid] = 0u;
    __syncthreads();
    int c = g_hicnt[b];
    if (c > HI_CAP) c = HI_CAP;
    for (int i = tid; i < c; i += 1024) {
        uint2 e = g_hi[b][i];
        atomicMax(&sgm[e.x >> 16], e.y);
    }
    __syncthreads();
    for (int i = tid; i < c; i += 1024) {
        uint2 e = g_hi[b][i];
        unsigned m = e.x >> 16;
        if (e.y == sgm[m])
            atomicMax(&g_lqv[(long long)b * N + (e.x & 0xFFFFu)], (unsigned)(M - (int)m));
    }
    __syncthreads();
    if (tid == 0) g_hicnt[b] = 0;           // reset for next replay
}

// ---------------------------------------------------------------------------
// Finalize assignment + build both masked-value histograms; the last block
// also computes the per-task threshold bin g_bt (saves compact's redundant
// per-block scan).
__global__ void __launch_bounds__(512)
finalize_hist_kernel(const float* __restrict__ prio,
                     float* __restrict__ out, long long lim) {
    __shared__ unsigned hp[NBIN];
    __shared__ unsigned hn[NBIN];
    __shared__ unsigned ss[512];
    __shared__ int s_last;
    int b = blockIdx.y;
    int tid = threadIdx.x;
#pragma unroll
    for (int j = 0; j < NBIN / 512; j++) {
        hp[tid + j * 512] = 0u;
        hn[tid + j * 512] = 0u;
    }
    __syncthreads();
    const float* pr = prio + (long long)b * N;
#pragma unroll
    for (int j = 0; j < 4; j++) {
        int n = blockIdx.x * 2048 + j * 512 + tid;
        long long o = (long long)b * N + n;
        int a = g_assigned[o];
        unsigned lv = g_lqv[o];
        if (lv) { a = (M - (int)lv) + 1; g_lqv[o] = 0u; }   // apply + reset
        g_assigned[o] = a;
        st(out, OFF_ASG + o, (float)a, lim);
        float v = pr[n];
        float vp = (a > 0)  ? __fadd_rn(v, 10.0f) : v;
        float vn = (a == 0) ? __fadd_rn(v, 10.0f) : v;
        atomicAdd(&hp[val_bin(vp)], 1u);
        atomicAdd(&hn[val_bin(vn)], 1u);
    }
    __syncthreads();
#pragma unroll
    for (int j = 0; j < NBIN / 512; j++) {
        int k = tid + j * 512;
        unsigned vp = hp[k], vn = hn[k];
        if (vp) atomicAdd(&g_hist[(2 * b) * NBIN + k], vp);
        if (vn) atomicAdd(&g_hist[(2 * b + 1) * NBIN + k], vn);
    }
    __syncthreads();
    if (tid == 0) {
        __threadfence();
        s_last = (atomicAdd(&g_fdone, 1u) == FBLOCKS - 1) ? 1 : 0;
    }
    __syncthreads();
    if (!s_last) return;
    // ---- last block: compute threshold bin for all 8 tasks ----
    for (int t = 0; t < 8; t++) {
        unsigned K = (t & 1) ? K_NEG : K_POS;
#pragma unroll
        for (int j = 0; j < 4; j++)
            hp[tid * 4 + j] = g_hist[t * NBIN + tid * 4 + j];
        unsigned cs = hp[tid * 4] + hp[tid * 4 + 1] + hp[tid * 4 + 2] + hp[tid * 4 + 3];
        ss[tid] = cs;
        __syncthreads();
        for (int off = 1; off < 512; off <<= 1) {
            unsigned v = (tid + off < 512) ? ss[tid + off] : 0u;
            __syncthreads();
            ss[tid] += v;
            __syncthreads();
        }
        unsigned cum = (tid == 511) ? 0u : ss[tid + 1];
        for (int d = tid * 4 + 3; d >= tid * 4; --d) {
            unsigned nc = cum + hp[d];
            if (nc >= K && cum < K) g_bt[t] = d;
            cum = nc;
        }
        __syncthreads();
    }
    if (tid == 0) g_fdone = 0u;             // reset for next replay
}

// ---------------------------------------------------------------------------
// Compact full 64-bit keys in bins >= g_bt[task].
__global__ void __launch_bounds__(256)
compact_kernel(const float* __restrict__ prio) {
    int task = blockIdx.y;
    int b = task >> 1, which = task & 1;
    int bt = g_bt[task];
    const float* pr = prio + (long long)b * N;
    const int* asg = g_assigned + (long long)b * N;
    int base = blockIdx.x * 1024;
#pragma unroll
    for (int j = 0; j < 4; j++) {
        int n = base + j * 256 + threadIdx.x;
        int a = asg[n];
        bool msk = which ? (a == 0) : (a > 0);
        float v = pr[n];
        float val = msk ? __fadd_rn(v, 10.0f) : v;
        if (val_bin(val) >= bt) {
            int p = atomicAdd(&g_ccnt[task], 1);
            if (p < CAND_CAP)
                g_cand[task][p] =
                    ((unsigned long long)__float_as_uint(val) << 32)
                  | (unsigned long long)(0xFFFFFFFFu - (unsigned)n);
        }
    }
}

// ---------------------------------------------------------------------------
// Sort candidates desc (64-bit keys: value desc, index asc = JAX order), emit
// sampled rows. Resets hist/ccnt.
__global__ void __launch_bounds__(1024)
sortsel_gather_kernel(const float4* __restrict__ bboxes,
                      const float4* __restrict__ gts,
                      const int* __restrict__ labels,
                      float* __restrict__ out, long long lim) {
    __shared__ unsigned long long skeys[CAND_CAP];
    int task = blockIdx.x;
    int b = task >> 1, which = task & 1;
    int K = which ? K_NEG : K_POS;
    int tid = threadIdx.x;
    int nc = g_ccnt[task];
    if (nc > CAND_CAP) nc = CAND_CAP;
    int P = 512;
    while (P < nc) P <<= 1;
    for (int i = tid; i < P; i += 1024)
        skeys[i] = (i < nc) ? g_cand[task][i] : 0ULL;
    __syncthreads();
    for (int kk = 2; kk <= P; kk <<= 1) {
        for (int j = kk >> 1; j > 0; j >>= 1) {
            for (int i = tid; i < P; i += 1024) {
                int l = i ^ j;
                if (l > i) {
                    unsigned long long a = skeys[i], c = skeys[l];
                    bool desc = ((i & kk) == 0);
                    if (desc ? (a < c) : (a > c)) { skeys[i] = c; skeys[l] = a; }
                }
            }
            __syncthreads();
        }
    }
    for (int i = tid; i < K; i += 1024) {
        unsigned idx = 0xFFFFFFFFu - (unsigned)(skeys[i] & 0xFFFFFFFFull);
        float4 bb = bboxes[(long long)b * N + idx];
        int a = g_assigned[(long long)b * N + idx];
        float4 tgt = make_float4(0.f, 0.f, 0.f, 0.f);
        float lab, val;
        int row;
        if (!which) {
            row = i;
            bool v = (a > 0);
            int gi = a - 1; if (gi < 0) gi = 0;
            if (v) {
                tgt = gts[b * M + gi];
                lab = (float)labels[b * M + gi];
            } else {
                lab = -1.0f;
            }
            val = v ? 1.0f : 0.0f;
        } else {
            row = K_POS + i;
            lab = 0.0f;
            val = (a == 0) ? 1.0f : 0.0f;
        }
        long long r = (long long)(b * NSAMP + row);
        long long ro = OFF_ROIS + r * 8;
        st(out, ro + 0, bb.x, lim); st(out, ro + 1, bb.y, lim);
        st(out, ro + 2, bb.z, lim); st(out, ro + 3, bb.w, lim);
        st(out, ro + 4, tgt.x, lim); st(out, ro + 5, tgt.y, lim);
        st(out, ro + 6, tgt.z, lim); st(out, ro + 7, tgt.w, lim);
        st(out, OFF_LAB + r, lab, lim);
        st(out, OFF_VAL + r, val, lim);
    }
    __syncthreads();
    for (int i = tid; i < NBIN; i += 1024) g_hist[task * NBIN + i] = 0u;
    if (tid == 0) g_ccnt[task] = 0;
}

extern "C" void kernel_launch(void* const* d_in, const int* in_sizes, int n_in,
                              void* d_out, int out_size) {
    const float4* bboxes = (const float4*)d_in[0];   // [B,N,4] f32
    const float4* gts    = (const float4*)d_in[1];   // [B,M,4] f32
    const int*    labels = (const int*)d_in[2];      // [B,M] i32
    const float*  prio   = (const float*)d_in[3];    // [B,N] f32
    float* out = (float*)d_out;
    long long lim = (long long)out_size;

    assign_fused_kernel<<<dim3(N / 512, B), 256>>>(bboxes, gts, out, lim);
    lq_refine_kernel<<<B, 1024>>>();
    finalize_hist_kernel<<<dim3(N / 2048, B), 512>>>(prio, out, lim);
    compact_kernel<<<dim3(N / 1024, 8), 256>>>(prio);
    sortsel_gather_kernel<<<8, 1024>>>(bboxes, gts, labels, out, lim);
}